// round 14
// baseline (speedup 1.0000x reference)
#include <cuda_runtime.h>
#include <cuda_fp16.h>
#include <math.h>
#include <stdint.h>

// Problem constants
#define NN   4096
#define DD   1024
#define HH   16
#define HDD  64
#define NOFF 24
#define KA   2048           // 2-term split-K: [Ah | Al] x [Bh | Bh]  (err ~2^-11)

// ---------------------------------------------------------------------------
// Scratch (__device__ globals; no cudaMalloc allowed)
// ---------------------------------------------------------------------------
__device__ __align__(16) __half g_xs  [(size_t)NN * KA];        // x split [hi|lo]
__device__ __align__(16) __half g_gs  [(size_t)NN * KA];        // gated split [hi|lo]
__device__ __align__(16) __half g_W1t [(size_t)(3*DD) * KA];    // WqkvT  [hi|hi]
__device__ __align__(16) __half g_Wgt [(size_t)DD * DD];        // WgateT [hi] single-plane
__device__ __align__(16) __half g_Wot [(size_t)DD * KA];        // WoutT  [hi|hi]
__device__ __align__(16) float  g_q   [(size_t)NN * DD];        // q  (fp32)
__device__ __align__(16) __half g_kv  [(size_t)NN * 2 * DD];    // [k | v] fp16, row 2048
__device__ __align__(16) float  g_gate[(size_t)NN * DD];

__constant__ int c_off[NOFF] = {0,1,2,3,4,6,8,12,16,24,32,48,64,96,128,
                                192,256,384,512,768,1024,1536,2048,3072};

// ---------------------------------------------------------------------------
// PTX helpers (sm_80-level only: compute_103 family target accepts these)
// ---------------------------------------------------------------------------
__device__ __forceinline__ uint32_t smem_u32(const void* p) {
    uint32_t a;
    asm("{ .reg .u64 t; cvta.to.shared.u64 t, %1; cvt.u32.u64 %0, t; }"
        : "=r"(a) : "l"(p));
    return a;
}
__device__ __forceinline__ void cp16(uint32_t s, const void* g) {
    asm volatile("cp.async.cg.shared.global [%0], [%1], 16;" :: "r"(s), "l"(g));
}
#define CP_COMMIT()  asm volatile("cp.async.commit_group;" ::: "memory")
#define CP_WAIT(n)   asm volatile("cp.async.wait_group %0;" :: "n"(n) : "memory")

__device__ __forceinline__ void ldm4(uint32_t* r, uint32_t addr) {
    asm volatile("ldmatrix.sync.aligned.m8n8.x4.shared.b16 {%0,%1,%2,%3}, [%4];"
                 : "=r"(r[0]), "=r"(r[1]), "=r"(r[2]), "=r"(r[3]) : "r"(addr));
}
__device__ __forceinline__ void mma_f16(float* d, const uint32_t* a, const uint32_t* b) {
    asm volatile(
        "mma.sync.aligned.m16n8k16.row.col.f32.f16.f16.f32 "
        "{%0,%1,%2,%3}, {%4,%5,%6,%7}, {%8,%9}, {%0,%1,%2,%3};"
        : "+f"(d[0]), "+f"(d[1]), "+f"(d[2]), "+f"(d[3])
        : "r"(a[0]), "r"(a[1]), "r"(a[2]), "r"(a[3]), "r"(b[0]), "r"(b[1]));
}

// ---------------------------------------------------------------------------
// Conversions
// ---------------------------------------------------------------------------
// x [4096,1024] f32 -> [hi | lo] fp16, row stride 2048
__global__ void conv_x_kernel(const float* __restrict__ X, __half* __restrict__ Y)
{
    int idx = blockIdx.x * blockDim.x + threadIdx.x;
    int m = idx >> 10, k = idx & 1023;
    float v = X[idx];
    __half hi = __float2half_rn(v);
    __half lo = __float2half_rn(v - __half2float(hi));
    size_t b = (size_t)m * KA;
    Y[b + k] = hi;
    Y[b + 1024 + k] = lo;
}

// W [1024, Ncols] f32 -> Wt rows [row_off + n] x 2048, blocks [hi | hi]
__global__ void conv_w2_kernel(const float* __restrict__ W,
                               __half* __restrict__ Wt, int Ncols, int row_off)
{
    __shared__ float t[32][33];
    const int tx = threadIdx.x, ty = threadIdx.y;
    const int n0 = blockIdx.x * 32, k0 = blockIdx.y * 32;
#pragma unroll
    for (int i = 0; i < 4; i++)
        t[ty + 8 * i][tx] = W[(size_t)(k0 + ty + 8 * i) * Ncols + n0 + tx];
    __syncthreads();
#pragma unroll
    for (int i = 0; i < 4; i++) {
        int n = n0 + ty + 8 * i;
        int k = k0 + tx;
        __half hi = __float2half_rn(t[tx][ty + 8 * i]);
        size_t b = (size_t)(row_off + n) * KA;
        Wt[b + k] = hi;
        Wt[b + 1024 + k] = hi;
    }
}

// Wgate [1024, 1024] f32 -> WgT [n][1024] single-plane fp16
__global__ void conv_wg_kernel(const float* __restrict__ W, __half* __restrict__ Wt)
{
    __shared__ float t[32][33];
    const int tx = threadIdx.x, ty = threadIdx.y;
    const int n0 = blockIdx.x * 32, k0 = blockIdx.y * 32;
#pragma unroll
    for (int i = 0; i < 4; i++)
        t[ty + 8 * i][tx] = W[(size_t)(k0 + ty + 8 * i) * DD + n0 + tx];
    __syncthreads();
#pragma unroll
    for (int i = 0; i < 4; i++) {
        int n = n0 + ty + 8 * i;
        int k = k0 + tx;
        Wt[(size_t)n * DD + k] = __float2half_rn(t[tx][ty + 8 * i]);
    }
}

// ---------------------------------------------------------------------------
// fp16 mma.sync GEMM: C[M, ldc-region] = A'[M, KEXT] @ Bt'[Nc, KEXT]^T + bias
// CTA tile 128x256, BK=32, 256 threads (2x4 warps, warp tile 64x64),
// 4-stage cp.async pipeline, padded 80B smem rows (conflict-free ldmatrix).
// ACT: 0 = fp32 out, 1 = fp32 sigmoid out, 2 = fp16 out.
// ---------------------------------------------------------------------------
#define GBM     128
#define GBN     256
#define GBK     32
#define ROW_B   80                    // 32 fp16 (64B) + 16B pad
#define A_BYTES (GBM * ROW_B)         // 10240
#define STAGE_B (A_BYTES + GBN * ROW_B)   // 30720
#define STAGES  4
#define SMEM_BYTES (STAGES * STAGE_B)     // 122880

template <int LDA, int LDB>
__device__ __forceinline__ void issue_stage(const char* Ab, const char* Bb,
                                            uint32_t sbase, int kc, int s, int tid)
{
    const char* Ak = Ab + (size_t)kc * (GBK * 2);
    const char* Bk = Bb + (size_t)kc * (GBK * 2);
    const uint32_t sA = sbase + s * STAGE_B;
    const uint32_t sB = sA + A_BYTES;
#pragma unroll
    for (int i = 0; i < 6; i++) {           // 1536 16B chunks / 256 threads
        int idx = tid + i * 256;
        int row = idx >> 2;
        int co  = (idx & 3) << 4;
        if (row < GBM)
            cp16(sA + row * ROW_B + co, Ak + (size_t)row * (LDA * 2) + co);
        else
            cp16(sB + (row - GBM) * ROW_B + co, Bk + (size_t)(row - GBM) * (LDB * 2) + co);
    }
    CP_COMMIT();
}

template <int KEXT, int LDA, int LDB, int ACT>
__global__ void __launch_bounds__(256)
gemm_mma(const __half* __restrict__ A,   // [M, LDA], K extent KEXT
         const __half* __restrict__ Bt,  // [Ncols, LDB], K extent KEXT
         const float* __restrict__ bias,
         void* __restrict__ Cv, int ldc)
{
    constexpr int NKC = KEXT / GBK;
    extern __shared__ char smem[];
    const int tid = threadIdx.x, lane = tid & 31, wid = tid >> 5;
    const int wm = wid & 1;        // 0..1 -> M offset wm*64
    const int wn = wid >> 1;       // 0..3 -> N offset wn*64
    const int m0 = blockIdx.y * GBM;
    const int n0 = blockIdx.x * GBN;
    const uint32_t sb = smem_u32(smem);

    const char* Ab = (const char*)A + (size_t)m0 * LDA * 2;
    const char* Bb = (const char*)Bt + (size_t)n0 * LDB * 2;

    float acc[4][8][4];
#pragma unroll
    for (int i = 0; i < 4; i++)
#pragma unroll
        for (int j = 0; j < 8; j++)
#pragma unroll
            for (int q = 0; q < 4; q++) acc[i][j][q] = 0.f;

    issue_stage<LDA, LDB>(Ab, Bb, sb, 0, 0, tid);
    issue_stage<LDA, LDB>(Ab, Bb, sb, 1, 1, tid);
    issue_stage<LDA, LDB>(Ab, Bb, sb, 2, 2, tid);

    const uint32_t aoff = (uint32_t)((wm * 64 + (lane & 15)) * ROW_B
                                     + (lane >> 4) * 16);
    const uint32_t boff = (uint32_t)A_BYTES
                        + (uint32_t)((wn * 64 + ((lane >> 4) & 1) * 8 + (lane & 7)) * ROW_B
                                     + ((lane >> 3) & 1) * 16);

    for (int kc = 0; kc < NKC; kc++) {
        CP_WAIT(2);
        __syncthreads();
        if (kc + 3 < NKC) issue_stage<LDA, LDB>(Ab, Bb, sb, kc + 3, (kc + 3) & 3, tid);
        else              CP_COMMIT();

        const uint32_t sA = sb + (kc & 3) * STAGE_B;
#pragma unroll
        for (int kp = 0; kp < 2; kp++) {
            uint32_t af[4][4], bf[4][4];
#pragma unroll
            for (int mi = 0; mi < 4; mi++)
                ldm4(af[mi], sA + aoff + mi * 16 * ROW_B + kp * 32);
#pragma unroll
            for (int j = 0; j < 4; j++)
                ldm4(bf[j], sA + boff + j * 16 * ROW_B + kp * 32);
#pragma unroll
            for (int mi = 0; mi < 4; mi++)
#pragma unroll
                for (int nj = 0; nj < 8; nj++)
                    mma_f16(acc[mi][nj], af[mi], &bf[nj >> 1][(nj & 1) * 2]);
        }
    }

    // Epilogue
    const int gid = lane >> 2, tig = lane & 3;
#pragma unroll
    for (int mi = 0; mi < 4; mi++) {
        const int r0 = m0 + wm * 64 + mi * 16 + gid;
#pragma unroll
        for (int nj = 0; nj < 8; nj++) {
            const int col = n0 + wn * 64 + nj * 8 + tig * 2;
            const float b0 = bias[col], b1 = bias[col + 1];
            float x0 = acc[mi][nj][0] + b0;
            float y0 = acc[mi][nj][1] + b1;
            float x1 = acc[mi][nj][2] + b0;
            float y1 = acc[mi][nj][3] + b1;
            if (ACT == 1) {
                x0 = 1.f / (1.f + __expf(-x0));
                y0 = 1.f / (1.f + __expf(-y0));
                x1 = 1.f / (1.f + __expf(-x1));
                y1 = 1.f / (1.f + __expf(-y1));
            }
            if (ACT == 2) {
                __half* C = (__half*)Cv;
                *(__half2*)(C + (size_t)r0 * ldc + col)       = __floats2half2_rn(x0, y0);
                *(__half2*)(C + (size_t)(r0 + 8) * ldc + col) = __floats2half2_rn(x1, y1);
            } else {
                float* C = (float*)Cv;
                float2 v;
                v.x = x0; v.y = y0;
                *(float2*)(C + (size_t)r0 * ldc + col) = v;
                v.x = x1; v.y = y1;
                *(float2*)(C + (size_t)(r0 + 8) * ldc + col) = v;
            }
        }
    }
}

// ---------------------------------------------------------------------------
// 24-tap dilated attention + gate multiply; q fp32, k/v fp16 (half gather
// traffic); writes 2-term split fp16 gs. One warp per (n, h).
// ---------------------------------------------------------------------------
__global__ void attn_kernel(const float* __restrict__ q_in,
                            const __half* __restrict__ kv,    // [N, 2048] = [k | v]
                            const float* __restrict__ gate,
                            const float* __restrict__ pos_bias,
                            __half* __restrict__ gs)
{
    const int gw   = (blockIdx.x * blockDim.x + threadIdx.x) >> 5;
    const int lane = threadIdx.x & 31;
    const int n = gw >> 4;
    const int h = gw & 15;
    if (n >= NN) return;

    const float scale = 0.125f;
    const int kcol = h * HDD + 2 * lane;
    const float2 q = *(const float2*)(q_in + (size_t)n * DD + kcol);

    float sc[NOFF];
#pragma unroll
    for (int o = 0; o < NOFF; o++) {
        const int src = n - c_off[o];
        float s = 0.f;
        if (src >= 0) {
            const __half2 kh = *(const __half2*)(kv + (size_t)src * (2 * DD) + kcol);
            const float2 k = __half22float2(kh);
            s = q.x * k.x + q.y * k.y;
        }
#pragma unroll
        for (int d = 16; d > 0; d >>= 1)
            s += __shfl_xor_sync(0xffffffffu, s, d);
        sc[o] = s * scale + pos_bias[o * HH + h];
    }

    float mx = sc[0];
#pragma unroll
    for (int o = 1; o < NOFF; o++) mx = fmaxf(mx, sc[o]);
    float den = 0.f;
#pragma unroll
    for (int o = 0; o < NOFF; o++) { sc[o] = __expf(sc[o] - mx); den += sc[o]; }
    const float inv = 1.f / den;

    float ax = 0.f, ay = 0.f;
#pragma unroll
    for (int o = 0; o < NOFF; o++) {
        const int src = n - c_off[o];
        if (src >= 0) {
            const __half2 vh = *(const __half2*)(kv + (size_t)src * (2 * DD) + DD + kcol);
            const float2 v = __half22float2(vh);
            const float w = sc[o] * inv;
            ax += w * v.x;
            ay += w * v.y;
        }
    }

    const size_t oidx = (size_t)n * DD + kcol;
    const float2 g = *(const float2*)(gate + oidx);
    const float v0 = ax * g.x;
    const float v1 = ay * g.y;

    // 2-term split write: [hi | lo]
    __half h0 = __float2half_rn(v0);
    __half h1 = __float2half_rn(v1);
    __half l0 = __float2half_rn(v0 - __half2float(h0));
    __half l1 = __float2half_rn(v1 - __half2float(h1));
    const size_t b = (size_t)n * KA + kcol;
    __half2 hp; hp.x = h0; hp.y = h1;
    __half2 lp; lp.x = l0; lp.y = l1;
    *(__half2*)(gs + b)        = hp;
    *(__half2*)(gs + b + 1024) = lp;
}

// ---------------------------------------------------------------------------
extern "C" void kernel_launch(void* const* d_in, const int* in_sizes, int n_in,
                              void* d_out, int out_size)
{
    const float* x     = (const float*)d_in[0];
    const float* Wqkv  = (const float*)d_in[1];
    const float* bqkv  = (const float*)d_in[2];
    const float* Wout  = (const float*)d_in[3];
    const float* bout  = (const float*)d_in[4];
    const float* Wgate = (const float*)d_in[5];
    const float* bgate = (const float*)d_in[6];
    const float* pbias = (const float*)d_in[7];
    float* out = (float*)d_out;

    __half *xs, *gs, *W1t, *Wgt, *Wot, *kvp;
    float *qp, *gate;
    cudaGetSymbolAddress((void**)&xs,   g_xs);
    cudaGetSymbolAddress((void**)&gs,   g_gs);
    cudaGetSymbolAddress((void**)&W1t,  g_W1t);
    cudaGetSymbolAddress((void**)&Wgt,  g_Wgt);
    cudaGetSymbolAddress((void**)&Wot,  g_Wot);
    cudaGetSymbolAddress((void**)&qp,   g_q);
    cudaGetSymbolAddress((void**)&kvp,  g_kv);
    cudaGetSymbolAddress((void**)&gate, g_gate);

    cudaFuncSetAttribute((const void*)gemm_mma<2048,2048,2048,0>,
                         cudaFuncAttributeMaxDynamicSharedMemorySize, SMEM_BYTES);
    cudaFuncSetAttribute((const void*)gemm_mma<2048,2048,2048,2>,
                         cudaFuncAttributeMaxDynamicSharedMemorySize, SMEM_BYTES);
    cudaFuncSetAttribute((const void*)gemm_mma<1024,2048,1024,1>,
                         cudaFuncAttributeMaxDynamicSharedMemorySize, SMEM_BYTES);

    // Conversions
    conv_x_kernel<<<(NN * DD) / 256, 256>>>(x, xs);
    conv_w2_kernel<<<dim3(3 * DD / 32, DD / 32), dim3(32, 8)>>>(Wqkv, W1t, 3 * DD, 0);
    conv_wg_kernel<<<dim3(DD / 32, DD / 32), dim3(32, 8)>>>(Wgate, Wgt);
    conv_w2_kernel<<<dim3(DD / 32, DD / 32), dim3(32, 8)>>>(Wout, Wot, DD, 0);

    // 1a) q = x @ Wq + bq            (fp32 out, cols 0-1023 of Wqkv)
    gemm_mma<2048,2048,2048,0><<<dim3(DD / GBN, NN / GBM), 256, SMEM_BYTES>>>(
        xs, W1t, bqkv, qp, DD);
    // 1b) [k|v] = x @ W[kv] + b[kv]  (fp16 out, cols 1024-3071)
    gemm_mma<2048,2048,2048,2><<<dim3(2 * DD / GBN, NN / GBM), 256, SMEM_BYTES>>>(
        xs, W1t + (size_t)DD * KA, bqkv + DD, kvp, 2 * DD);
    // 2) gate = sigmoid(x @ Wgate + bgate)  (single-plane fp16, K=1024)
    gemm_mma<1024,2048,1024,1><<<dim3(DD / GBN, NN / GBM), 256, SMEM_BYTES>>>(
        xs, Wgt, bgate, gate, DD);
    // 3) attention + gate multiply -> gs (2-term split fp16)
    attn_kernel<<<(NN * HH * 32) / 256, 256>>>(qp, kvp, gate, pbias, gs);
    // 4) out = gated @ Wout + bout   (2-term fp16 split, K'=2048)
    gemm_mma<2048,2048,2048,0><<<dim3(DD / GBN, NN / GBM), 256, SMEM_BYTES>>>(
        gs, Wot, bout, out, DD);
}

// round 15
// speedup vs baseline: 1.0109x; 1.0109x over previous
#include <cuda_runtime.h>
#include <cuda_fp16.h>
#include <math.h>
#include <stdint.h>

// Problem constants
#define NN   4096
#define DD   1024
#define HH   16
#define HDD  64
#define NOFF 24
#define KA   2048           // 2-term split-K: [Ah | Al] x [Bh | Bh]  (err ~2^-11)

// ---------------------------------------------------------------------------
// Scratch (__device__ globals; no cudaMalloc allowed)
// ---------------------------------------------------------------------------
__device__ __align__(16) __half g_xs  [(size_t)NN * KA];        // x split [hi|lo]
__device__ __align__(16) __half g_gs  [(size_t)NN * KA];        // gated split [hi|lo]
__device__ __align__(16) __half g_W1t [(size_t)(3*DD) * KA];    // WqkvT  [hi|hi]
__device__ __align__(16) __half g_Wgt [(size_t)DD * DD];        // WgateT [hi] single-plane
__device__ __align__(16) __half g_Wot [(size_t)DD * KA];        // WoutT  [hi|hi]
__device__ __align__(16) float  g_q   [(size_t)NN * DD];        // q  (fp32)
__device__ __align__(16) __half g_kv  [(size_t)NN * 2 * DD];    // [k | v] fp16, row 2048
__device__ __align__(16) float  g_gate[(size_t)NN * DD];

__constant__ int c_off[NOFF] = {0,1,2,3,4,6,8,12,16,24,32,48,64,96,128,
                                192,256,384,512,768,1024,1536,2048,3072};

// ---------------------------------------------------------------------------
// PTX helpers (sm_80-level only: compute_103 family target accepts these)
// ---------------------------------------------------------------------------
__device__ __forceinline__ uint32_t smem_u32(const void* p) {
    uint32_t a;
    asm("{ .reg .u64 t; cvta.to.shared.u64 t, %1; cvt.u32.u64 %0, t; }"
        : "=r"(a) : "l"(p));
    return a;
}
__device__ __forceinline__ void cp16(uint32_t s, const void* g) {
    asm volatile("cp.async.cg.shared.global [%0], [%1], 16;" :: "r"(s), "l"(g));
}
#define CP_COMMIT()  asm volatile("cp.async.commit_group;" ::: "memory")
#define CP_WAIT(n)   asm volatile("cp.async.wait_group %0;" :: "n"(n) : "memory")

__device__ __forceinline__ void ldm4(uint32_t* r, uint32_t addr) {
    asm volatile("ldmatrix.sync.aligned.m8n8.x4.shared.b16 {%0,%1,%2,%3}, [%4];"
                 : "=r"(r[0]), "=r"(r[1]), "=r"(r[2]), "=r"(r[3]) : "r"(addr));
}
__device__ __forceinline__ void mma_f16(float* d, const uint32_t* a, const uint32_t* b) {
    asm volatile(
        "mma.sync.aligned.m16n8k16.row.col.f32.f16.f16.f32 "
        "{%0,%1,%2,%3}, {%4,%5,%6,%7}, {%8,%9}, {%0,%1,%2,%3};"
        : "+f"(d[0]), "+f"(d[1]), "+f"(d[2]), "+f"(d[3])
        : "r"(a[0]), "r"(a[1]), "r"(a[2]), "r"(a[3]), "r"(b[0]), "r"(b[1]));
}

// ---------------------------------------------------------------------------
// Conversions
// ---------------------------------------------------------------------------
// x [4096,1024] f32 -> [hi | lo] fp16, row stride 2048
__global__ void conv_x_kernel(const float* __restrict__ X, __half* __restrict__ Y)
{
    int idx = blockIdx.x * blockDim.x + threadIdx.x;
    int m = idx >> 10, k = idx & 1023;
    float v = X[idx];
    __half hi = __float2half_rn(v);
    __half lo = __float2half_rn(v - __half2float(hi));
    size_t b = (size_t)m * KA;
    Y[b + k] = hi;
    Y[b + 1024 + k] = lo;
}

// W [1024, Ncols] f32 -> Wt rows [row_off + n] x 2048, blocks [hi | hi]
__global__ void conv_w2_kernel(const float* __restrict__ W,
                               __half* __restrict__ Wt, int Ncols, int row_off)
{
    __shared__ float t[32][33];
    const int tx = threadIdx.x, ty = threadIdx.y;
    const int n0 = blockIdx.x * 32, k0 = blockIdx.y * 32;
#pragma unroll
    for (int i = 0; i < 4; i++)
        t[ty + 8 * i][tx] = W[(size_t)(k0 + ty + 8 * i) * Ncols + n0 + tx];
    __syncthreads();
#pragma unroll
    for (int i = 0; i < 4; i++) {
        int n = n0 + ty + 8 * i;
        int k = k0 + tx;
        __half hi = __float2half_rn(t[tx][ty + 8 * i]);
        size_t b = (size_t)(row_off + n) * KA;
        Wt[b + k] = hi;
        Wt[b + 1024 + k] = hi;
    }
}

// Wgate [1024, 1024] f32 -> WgT [n][1024] single-plane fp16
__global__ void conv_wg_kernel(const float* __restrict__ W, __half* __restrict__ Wt)
{
    __shared__ float t[32][33];
    const int tx = threadIdx.x, ty = threadIdx.y;
    const int n0 = blockIdx.x * 32, k0 = blockIdx.y * 32;
#pragma unroll
    for (int i = 0; i < 4; i++)
        t[ty + 8 * i][tx] = W[(size_t)(k0 + ty + 8 * i) * DD + n0 + tx];
    __syncthreads();
#pragma unroll
    for (int i = 0; i < 4; i++) {
        int n = n0 + ty + 8 * i;
        int k = k0 + tx;
        Wt[(size_t)n * DD + k] = __float2half_rn(t[tx][ty + 8 * i]);
    }
}

// ---------------------------------------------------------------------------
// fp16 mma.sync GEMM: C = A'[M,KEXT] @ Bt'[Nc,KEXT]^T + bias
// CTA tile 128x256, BK=32, 256 threads (2x4 warps, warp tile 64x64),
// 4-stage cp.async pipeline, padded 80B smem rows (conflict-free ldmatrix).
// MODE: 0 = fp32 out, 1 = fp32 sigmoid out,
//       3 = qkv split: n0 < 1024 -> fp32 q (C0), n0 >= 1024 -> fp16 kv (C1).
// ---------------------------------------------------------------------------
#define GBM     128
#define GBN     256
#define GBK     32
#define ROW_B   80                    // 32 fp16 (64B) + 16B pad
#define A_BYTES (GBM * ROW_B)         // 10240
#define STAGE_B (A_BYTES + GBN * ROW_B)   // 30720
#define STAGES  4
#define SMEM_BYTES (STAGES * STAGE_B)     // 122880

template <int LDA, int LDB>
__device__ __forceinline__ void issue_stage(const char* Ab, const char* Bb,
                                            uint32_t sbase, int kc, int s, int tid)
{
    const char* Ak = Ab + (size_t)kc * (GBK * 2);
    const char* Bk = Bb + (size_t)kc * (GBK * 2);
    const uint32_t sA = sbase + s * STAGE_B;
    const uint32_t sB = sA + A_BYTES;
#pragma unroll
    for (int i = 0; i < 6; i++) {           // 1536 16B chunks / 256 threads
        int idx = tid + i * 256;
        int row = idx >> 2;
        int co  = (idx & 3) << 4;
        if (row < GBM)
            cp16(sA + row * ROW_B + co, Ak + (size_t)row * (LDA * 2) + co);
        else
            cp16(sB + (row - GBM) * ROW_B + co, Bk + (size_t)(row - GBM) * (LDB * 2) + co);
    }
    CP_COMMIT();
}

template <int KEXT, int LDA, int LDB, int MODE>
__global__ void __launch_bounds__(256)
gemm_mma(const __half* __restrict__ A,   // [M, LDA], K extent KEXT
         const __half* __restrict__ Bt,  // [Ncols, LDB], K extent KEXT
         const float* __restrict__ bias,
         float* __restrict__ C0, int ldc0,
         __half* __restrict__ C1, int ldc1)
{
    constexpr int NKC = KEXT / GBK;
    extern __shared__ char smem[];
    const int tid = threadIdx.x, lane = tid & 31, wid = tid >> 5;
    const int wm = wid & 1;        // 0..1 -> M offset wm*64
    const int wn = wid >> 1;       // 0..3 -> N offset wn*64
    const int m0 = blockIdx.y * GBM;
    const int n0 = blockIdx.x * GBN;
    const uint32_t sb = smem_u32(smem);

    const char* Ab = (const char*)A + (size_t)m0 * LDA * 2;
    const char* Bb = (const char*)Bt + (size_t)n0 * LDB * 2;

    float acc[4][8][4];
#pragma unroll
    for (int i = 0; i < 4; i++)
#pragma unroll
        for (int j = 0; j < 8; j++)
#pragma unroll
            for (int q = 0; q < 4; q++) acc[i][j][q] = 0.f;

    issue_stage<LDA, LDB>(Ab, Bb, sb, 0, 0, tid);
    issue_stage<LDA, LDB>(Ab, Bb, sb, 1, 1, tid);
    issue_stage<LDA, LDB>(Ab, Bb, sb, 2, 2, tid);

    const uint32_t aoff = (uint32_t)((wm * 64 + (lane & 15)) * ROW_B
                                     + (lane >> 4) * 16);
    const uint32_t boff = (uint32_t)A_BYTES
                        + (uint32_t)((wn * 64 + ((lane >> 4) & 1) * 8 + (lane & 7)) * ROW_B
                                     + ((lane >> 3) & 1) * 16);

    for (int kc = 0; kc < NKC; kc++) {
        CP_WAIT(2);
        __syncthreads();
        if (kc + 3 < NKC) issue_stage<LDA, LDB>(Ab, Bb, sb, kc + 3, (kc + 3) & 3, tid);
        else              CP_COMMIT();

        const uint32_t sA = sb + (kc & 3) * STAGE_B;
#pragma unroll
        for (int kp = 0; kp < 2; kp++) {
            uint32_t af[4][4], bf[4][4];
#pragma unroll
            for (int mi = 0; mi < 4; mi++)
                ldm4(af[mi], sA + aoff + mi * 16 * ROW_B + kp * 32);
#pragma unroll
            for (int j = 0; j < 4; j++)
                ldm4(bf[j], sA + boff + j * 16 * ROW_B + kp * 32);
#pragma unroll
            for (int mi = 0; mi < 4; mi++)
#pragma unroll
                for (int nj = 0; nj < 8; nj++)
                    mma_f16(acc[mi][nj], af[mi], &bf[nj >> 1][(nj & 1) * 2]);
        }
    }

    // Epilogue
    const int gid = lane >> 2, tig = lane & 3;
    const bool to_half = (MODE == 3) && (n0 >= DD);   // per-CTA uniform
    const int ncol = to_half ? (n0 - DD) : n0;        // local col base in target
    const int ldc = to_half ? ldc1 : ldc0;
#pragma unroll
    for (int mi = 0; mi < 4; mi++) {
        const int r0 = m0 + wm * 64 + mi * 16 + gid;
#pragma unroll
        for (int nj = 0; nj < 8; nj++) {
            const int gcol = n0 + wn * 64 + nj * 8 + tig * 2;   // global bias col
            const int col  = ncol + wn * 64 + nj * 8 + tig * 2; // target col
            const float b0 = bias[gcol], b1 = bias[gcol + 1];
            float x0 = acc[mi][nj][0] + b0;
            float y0 = acc[mi][nj][1] + b1;
            float x1 = acc[mi][nj][2] + b0;
            float y1 = acc[mi][nj][3] + b1;
            if (MODE == 1) {
                x0 = 1.f / (1.f + __expf(-x0));
                y0 = 1.f / (1.f + __expf(-y0));
                x1 = 1.f / (1.f + __expf(-x1));
                y1 = 1.f / (1.f + __expf(-y1));
            }
            if (to_half) {
                *(__half2*)(C1 + (size_t)r0 * ldc + col)       = __floats2half2_rn(x0, y0);
                *(__half2*)(C1 + (size_t)(r0 + 8) * ldc + col) = __floats2half2_rn(x1, y1);
            } else {
                float2 v;
                v.x = x0; v.y = y0;
                *(float2*)(C0 + (size_t)r0 * ldc + col) = v;
                v.x = x1; v.y = y1;
                *(float2*)(C0 + (size_t)(r0 + 8) * ldc + col) = v;
            }
        }
    }
}

// ---------------------------------------------------------------------------
// 24-tap dilated attention + gate multiply; q fp32, k/v fp16 (half gather
// traffic); writes 2-term split fp16 gs. One warp per (n, h).
// ---------------------------------------------------------------------------
__global__ void attn_kernel(const float* __restrict__ q_in,
                            const __half* __restrict__ kv,    // [N, 2048] = [k | v]
                            const float* __restrict__ gate,
                            const float* __restrict__ pos_bias,
                            __half* __restrict__ gs)
{
    const int gw   = (blockIdx.x * blockDim.x + threadIdx.x) >> 5;
    const int lane = threadIdx.x & 31;
    const int n = gw >> 4;
    const int h = gw & 15;
    if (n >= NN) return;

    const float scale = 0.125f;
    const int kcol = h * HDD + 2 * lane;
    const float2 q = *(const float2*)(q_in + (size_t)n * DD + kcol);

    float sc[NOFF];
#pragma unroll
    for (int o = 0; o < NOFF; o++) {
        const int src = n - c_off[o];
        float s = 0.f;
        if (src >= 0) {
            const __half2 kh = *(const __half2*)(kv + (size_t)src * (2 * DD) + kcol);
            const float2 k = __half22float2(kh);
            s = q.x * k.x + q.y * k.y;
        }
#pragma unroll
        for (int d = 16; d > 0; d >>= 1)
            s += __shfl_xor_sync(0xffffffffu, s, d);
        sc[o] = s * scale + pos_bias[o * HH + h];
    }

    float mx = sc[0];
#pragma unroll
    for (int o = 1; o < NOFF; o++) mx = fmaxf(mx, sc[o]);
    float den = 0.f;
#pragma unroll
    for (int o = 0; o < NOFF; o++) { sc[o] = __expf(sc[o] - mx); den += sc[o]; }
    const float inv = 1.f / den;

    float ax = 0.f, ay = 0.f;
#pragma unroll
    for (int o = 0; o < NOFF; o++) {
        const int src = n - c_off[o];
        if (src >= 0) {
            const __half2 vh = *(const __half2*)(kv + (size_t)src * (2 * DD) + DD + kcol);
            const float2 v = __half22float2(vh);
            const float w = sc[o] * inv;
            ax += w * v.x;
            ay += w * v.y;
        }
    }

    const size_t oidx = (size_t)n * DD + kcol;
    const float2 g = *(const float2*)(gate + oidx);
    const float v0 = ax * g.x;
    const float v1 = ay * g.y;

    // 2-term split write: [hi | lo]
    __half h0 = __float2half_rn(v0);
    __half h1 = __float2half_rn(v1);
    __half l0 = __float2half_rn(v0 - __half2float(h0));
    __half l1 = __float2half_rn(v1 - __half2float(h1));
    const size_t b = (size_t)n * KA + kcol;
    __half2 hp; hp.x = h0; hp.y = h1;
    __half2 lp; lp.x = l0; lp.y = l1;
    *(__half2*)(gs + b)        = hp;
    *(__half2*)(gs + b + 1024) = lp;
}

// ---------------------------------------------------------------------------
extern "C" void kernel_launch(void* const* d_in, const int* in_sizes, int n_in,
                              void* d_out, int out_size)
{
    const float* x     = (const float*)d_in[0];
    const float* Wqkv  = (const float*)d_in[1];
    const float* bqkv  = (const float*)d_in[2];
    const float* Wout  = (const float*)d_in[3];
    const float* bout  = (const float*)d_in[4];
    const float* Wgate = (const float*)d_in[5];
    const float* bgate = (const float*)d_in[6];
    const float* pbias = (const float*)d_in[7];
    float* out = (float*)d_out;

    __half *xs, *gs, *W1t, *Wgt, *Wot, *kvp;
    float *qp, *gate;
    cudaGetSymbolAddress((void**)&xs,   g_xs);
    cudaGetSymbolAddress((void**)&gs,   g_gs);
    cudaGetSymbolAddress((void**)&W1t,  g_W1t);
    cudaGetSymbolAddress((void**)&Wgt,  g_Wgt);
    cudaGetSymbolAddress((void**)&Wot,  g_Wot);
    cudaGetSymbolAddress((void**)&qp,   g_q);
    cudaGetSymbolAddress((void**)&kvp,  g_kv);
    cudaGetSymbolAddress((void**)&gate, g_gate);

    cudaFuncSetAttribute((const void*)gemm_mma<2048,2048,2048,3>,
                         cudaFuncAttributeMaxDynamicSharedMemorySize, SMEM_BYTES);
    cudaFuncSetAttribute((const void*)gemm_mma<2048,2048,2048,0>,
                         cudaFuncAttributeMaxDynamicSharedMemorySize, SMEM_BYTES);
    cudaFuncSetAttribute((const void*)gemm_mma<1024,2048,1024,1>,
                         cudaFuncAttributeMaxDynamicSharedMemorySize, SMEM_BYTES);

    // Conversions
    conv_x_kernel<<<(NN * DD) / 256, 256>>>(x, xs);
    conv_w2_kernel<<<dim3(3 * DD / 32, DD / 32), dim3(32, 8)>>>(Wqkv, W1t, 3 * DD, 0);
    conv_wg_kernel<<<dim3(DD / 32, DD / 32), dim3(32, 8)>>>(Wgate, Wgt);
    conv_w2_kernel<<<dim3(DD / 32, DD / 32), dim3(32, 8)>>>(Wout, Wot, DD, 0);

    // 1) [q | k | v] = x @ Wqkv + bqkv  — single 384-CTA launch;
    //    cols < 1024 -> fp32 q, cols >= 1024 -> fp16 kv (per-CTA dispatch)
    gemm_mma<2048,2048,2048,3><<<dim3(3 * DD / GBN, NN / GBM), 256, SMEM_BYTES>>>(
        xs, W1t, bqkv, qp, DD, kvp, 2 * DD);
    // 2) gate = sigmoid(x @ Wgate + bgate)  (single-plane fp16, K=1024)
    gemm_mma<1024,2048,1024,1><<<dim3(DD / GBN, NN / GBM), 256, SMEM_BYTES>>>(
        xs, Wgt, bgate, gate, DD, (__half*)0, 0);
    // 3) attention + gate multiply -> gs (2-term split fp16)
    attn_kernel<<<(NN * HH * 32) / 256, 256>>>(qp, kvp, gate, pbias, gs);
    // 4) out = gated @ Wout + bout       (2-term fp16 split, K'=2048)
    gemm_mma<2048,2048,2048,0><<<dim3(DD / GBN, NN / GBM), 256, SMEM_BYTES>>>(
        gs, Wot, bout, out, DD, (__half*)0, 0);
}